// round 4
// baseline (speedup 1.0000x reference)
#include <cuda_runtime.h>
#include <math.h>

#define BB   128
#define GG   37
#define NP   (GG*GG)          // 1369 patches
#define DD   768
#define CC   5                // cues: cls + 4 regs
#define SS   (1 + 4 + NP)     // 1374 tokens per batch
#define CH   8                // patch chunks per batch (kernel-1 blocks per batch)
#define CPB  ((NP + CH - 1) / CH)   // 172 patches per chunk
#define NW   8                // warps per block
#define PP   4                // patches per warp per inner iteration
#define FLT_BIG 3.402823466e38f

// Cross-kernel scratch: per (batch, cue, chunk) partial argmax.
__device__ float g_pval[BB * CC * CH];
__device__ int   g_pidx[BB * CC * CH];

// ---------------------------------------------------------------------------
// Kernel 1: streaming dot-products cue[c] . patch[p], per-chunk argmax.
// Grid: (BB, CH). Block: 256 threads (8 warps).
// Each warp handles groups of 4 consecutive patches; lane l reads float4 at
// offset 4*l within 128-float segments -> fully coalesced 512B LDG requests.
// ---------------------------------------------------------------------------
__global__ __launch_bounds__(256)
void sim_argmax_kernel(const float* __restrict__ tokens)
{
    __shared__ float cue_s[CC * DD];     // 15360 B
    __shared__ float s_bval[NW * CC];
    __shared__ int   s_bidx[NW * CC];

    const int b     = blockIdx.x;
    const int chunk = blockIdx.y;
    const int tid   = threadIdx.x;
    const int w     = tid >> 5;
    const int lane  = tid & 31;

    const float* tb = tokens + (size_t)b * SS * DD;

    // stage the 5 cue rows (tokens s = 0..4) into shared memory
    for (int i = tid; i < CC * DD; i += 256) cue_s[i] = tb[i];
    __syncthreads();

    const int start = chunk * CPB;
    const int end   = min(start + CPB, NP);

    float bval[CC];
    int   bidx[CC];
#pragma unroll
    for (int c = 0; c < CC; c++) { bval[c] = -FLT_BIG; bidx[c] = 0x7fffffff; }

    const float4* cue4 = reinterpret_cast<const float4*>(cue_s);

    for (int base = start + w * PP; base < end; base += NW * PP) {
        int  p[PP];
        bool valid[PP];
        const float4* rows[PP];
#pragma unroll
        for (int i = 0; i < PP; i++) {
            p[i]     = base + i;
            valid[i] = (p[i] < end);
            int pa   = valid[i] ? p[i] : start;    // clamp to a safe in-range patch
            rows[i]  = reinterpret_cast<const float4*>(tb + (size_t)(5 + pa) * DD);
        }

        float acc[CC][PP];
#pragma unroll
        for (int c = 0; c < CC; c++)
#pragma unroll
            for (int i = 0; i < PP; i++) acc[c][i] = 0.0f;

#pragma unroll
        for (int j = 0; j < 6; j++) {              // 6 * 32 float4 = 192 float4 = 768 floats
            const int off = j * 32 + lane;
            float4 v[PP];
#pragma unroll
            for (int i = 0; i < PP; i++) v[i] = rows[i][off];
#pragma unroll
            for (int c = 0; c < CC; c++) {
                const float4 q = cue4[c * 192 + off];
#pragma unroll
                for (int i = 0; i < PP; i++) {
                    acc[c][i] += v[i].x * q.x + v[i].y * q.y
                               + v[i].z * q.z + v[i].w * q.w;
                }
            }
        }

        // warp-butterfly reduce each of the 20 partial dots; result in all lanes
#pragma unroll
        for (int c = 0; c < CC; c++) {
#pragma unroll
            for (int i = 0; i < PP; i++) {
                float v = acc[c][i];
                v += __shfl_xor_sync(0xffffffffu, v, 16);
                v += __shfl_xor_sync(0xffffffffu, v, 8);
                v += __shfl_xor_sync(0xffffffffu, v, 4);
                v += __shfl_xor_sync(0xffffffffu, v, 2);
                v += __shfl_xor_sync(0xffffffffu, v, 1);
                if (valid[i]) {
                    if (v > bval[c] || (v == bval[c] && p[i] < bidx[c])) {
                        bval[c] = v;
                        bidx[c] = p[i];
                    }
                }
            }
        }
    }

    if (lane == 0) {
#pragma unroll
        for (int c = 0; c < CC; c++) {
            s_bval[w * CC + c] = bval[c];
            s_bidx[w * CC + c] = bidx[c];
        }
    }
    __syncthreads();

    if (tid < CC) {
        const int c = tid;
        float bv = -FLT_BIG;
        int   bi = 0x7fffffff;
        for (int ww = 0; ww < NW; ww++) {
            float v  = s_bval[ww * CC + c];
            int   ix = s_bidx[ww * CC + c];
            if (v > bv || (v == bv && ix < bi)) { bv = v; bi = ix; }
        }
        g_pval[(b * CC + c) * CH + chunk] = bv;
        g_pidx[(b * CC + c) * CH + chunk] = bi;
    }
}

// ---------------------------------------------------------------------------
// Kernel 2: merge chunk partials -> argmax (h,w); 3x3 clipped window mean;
// L2-normalize roi and cue; write output (B, 10, 768).
// Grid: (CC, BB). Block: 384 threads; thread t owns d = t and t+384.
// ---------------------------------------------------------------------------
__global__ __launch_bounds__(384)
void pool_norm_kernel(const float* __restrict__ tokens, float* __restrict__ out)
{
    const int c   = blockIdx.x;
    const int b   = blockIdx.y;
    const int tid = threadIdx.x;

    __shared__ int   s_win[4];     // h0, h1, w0, w1
    __shared__ float s_red[26];

    if (tid == 0) {
        float bv = -FLT_BIG;
        int   bi = 0x7fffffff;
        for (int ch = 0; ch < CH; ch++) {
            float v  = g_pval[(b * CC + c) * CH + ch];
            int   ix = g_pidx[(b * CC + c) * CH + ch];
            if (v > bv || (v == bv && ix < bi)) { bv = v; bi = ix; }
        }
        const int h = bi / GG;
        const int w = bi % GG;
        s_win[0] = max(h - 1, 0);
        s_win[1] = min(h + 1, GG - 1);
        s_win[2] = max(w - 1, 0);
        s_win[3] = min(w + 1, GG - 1);
    }
    __syncthreads();

    const int h0 = s_win[0], h1 = s_win[1], w0 = s_win[2], w1 = s_win[3];
    const float inv_count = 1.0f / (float)((h1 - h0 + 1) * (w1 - w0 + 1));
    const float* tb = tokens + (size_t)b * SS * DD;

    float roi[2], q[2];
    float sr = 0.0f, sq = 0.0f;
#pragma unroll
    for (int k = 0; k < 2; k++) {
        const int d = tid + 384 * k;
        float s = 0.0f;
        for (int hh = h0; hh <= h1; hh++)
            for (int ww = w0; ww <= w1; ww++)
                s += tb[(size_t)(5 + hh * GG + ww) * DD + d];
        roi[k] = s * inv_count;
        q[k]   = tb[(size_t)c * DD + d];
        sr += roi[k] * roi[k];
        sq += q[k] * q[k];
    }

    // block-reduce the two squared norms
#pragma unroll
    for (int o = 16; o; o >>= 1) {
        sr += __shfl_xor_sync(0xffffffffu, sr, o);
        sq += __shfl_xor_sync(0xffffffffu, sq, o);
    }
    const int w = tid >> 5, lane = tid & 31;
    if (lane == 0) { s_red[w] = sr; s_red[12 + w] = sq; }
    __syncthreads();
    if (tid == 0) {
        float a = 0.0f, bs = 0.0f;
        for (int i = 0; i < 12; i++) { a += s_red[i]; bs += s_red[12 + i]; }
        s_red[24] = a;
        s_red[25] = bs;
    }
    __syncthreads();

    const float rinv = 1.0f / fmaxf(sqrtf(s_red[24]), 1e-12f);
    const float qinv = 1.0f / fmaxf(sqrtf(s_red[25]), 1e-12f);

    float* ob = out + (size_t)b * 10 * DD;
#pragma unroll
    for (int k = 0; k < 2; k++) {
        const int d = tid + 384 * k;
        ob[(size_t)c * DD + d]       = q[k] * qinv;      // normalized cue
        ob[(size_t)(5 + c) * DD + d] = roi[k] * rinv;    // normalized roi
    }
}

extern "C" void kernel_launch(void* const* d_in, const int* in_sizes, int n_in,
                              void* d_out, int out_size)
{
    const float* tokens = (const float*)d_in[0];
    float* out = (float*)d_out;

    dim3 g1(BB, CH);     // 128 x 8 = 1024 blocks
    sim_argmax_kernel<<<g1, 256>>>(tokens);

    dim3 g2(CC, BB);     // 5 x 128 = 640 blocks
    pool_norm_kernel<<<g2, 384>>>(tokens, out);
}

// round 9
// speedup vs baseline: 1.6156x; 1.6156x over previous
#include <cuda_runtime.h>
#include <math.h>

#define BB   128
#define GG   37
#define NP   (GG*GG)          // 1369 patches
#define DD   768
#define CC   5                // cues: cls + 4 regs
#define SS   (1 + 4 + NP)     // 1374 tokens per batch
#define CH   8                // patch chunks per batch (kernel-1 blocks per batch)
#define CPB  ((NP + CH - 1) / CH)   // 172 patches per chunk
#define NW   8                // warps per block
#define PP   4                // patches per warp per inner iteration
#define FLT_BIG 3.402823466e38f

// Cross-kernel scratch: per (batch, cue, chunk) partial argmax.
__device__ float g_pval[BB * CC * CH];
__device__ int   g_pidx[BB * CC * CH];

// ---------------------------------------------------------------------------
// Kernel 1: streaming dot-products cue[c] . patch[p], per-chunk argmax.
// Grid: (BB, CH). Block: 256 threads (8 warps).
// __launch_bounds__(256, 4): cap regs ~64 so 4 CTAs (32 warps) fit per SM —
// memory concurrency is the limiter, not issue slots.
// ---------------------------------------------------------------------------
__global__ __launch_bounds__(256, 4)
void sim_argmax_kernel(const float* __restrict__ tokens)
{
    __shared__ float cue_s[CC * DD];     // 15360 B
    __shared__ float s_bval[NW * CC];
    __shared__ int   s_bidx[NW * CC];

    const int b     = blockIdx.x;
    const int chunk = blockIdx.y;
    const int tid   = threadIdx.x;
    const int w     = tid >> 5;
    const int lane  = tid & 31;

    const float* tb = tokens + (size_t)b * SS * DD;

    // stage the 5 cue rows (tokens s = 0..4) into shared memory
    for (int i = tid; i < CC * DD; i += 256) cue_s[i] = tb[i];
    __syncthreads();

    const int start = chunk * CPB;
    const int end   = min(start + CPB, NP);

    float bval[CC];
    int   bidx[CC];
#pragma unroll
    for (int c = 0; c < CC; c++) { bval[c] = -FLT_BIG; bidx[c] = 0x7fffffff; }

    const float4* cue4 = reinterpret_cast<const float4*>(cue_s);
    const float4* pb4  = reinterpret_cast<const float4*>(tb + 5 * DD);

    for (int base = start + w * PP; base < end; base += NW * PP) {

        float acc[CC][PP];
#pragma unroll
        for (int c = 0; c < CC; c++)
#pragma unroll
            for (int i = 0; i < PP; i++) acc[c][i] = 0.0f;

        // limited unroll keeps only one j-step of patch data (16 regs) live
#pragma unroll 2
        for (int j = 0; j < 6; j++) {              // 6 * 32 float4 = 768 floats
            const int off = j * 32 + lane;
            float4 v[PP];
#pragma unroll
            for (int i = 0; i < PP; i++) {
                // predicated load: invalid tail lanes contribute 0 and no traffic
                if (base + i < end) {
                    v[i] = pb4[(size_t)(base + i) * 192 + off];
                } else {
                    v[i] = make_float4(0.f, 0.f, 0.f, 0.f);
                }
            }
#pragma unroll
            for (int c = 0; c < CC; c++) {
                const float4 q = cue4[c * 192 + off];
#pragma unroll
                for (int i = 0; i < PP; i++) {
                    acc[c][i] += v[i].x * q.x + v[i].y * q.y
                               + v[i].z * q.z + v[i].w * q.w;
                }
            }
        }

        // warp-butterfly reduce each of the 20 partial dots; result in all lanes
#pragma unroll
        for (int c = 0; c < CC; c++) {
#pragma unroll
            for (int i = 0; i < PP; i++) {
                float v = acc[c][i];
                v += __shfl_xor_sync(0xffffffffu, v, 16);
                v += __shfl_xor_sync(0xffffffffu, v, 8);
                v += __shfl_xor_sync(0xffffffffu, v, 4);
                v += __shfl_xor_sync(0xffffffffu, v, 2);
                v += __shfl_xor_sync(0xffffffffu, v, 1);
                const int p = base + i;
                if (p < end) {
                    if (v > bval[c] || (v == bval[c] && p < bidx[c])) {
                        bval[c] = v;
                        bidx[c] = p;
                    }
                }
            }
        }
    }

    if (lane == 0) {
#pragma unroll
        for (int c = 0; c < CC; c++) {
            s_bval[w * CC + c] = bval[c];
            s_bidx[w * CC + c] = bidx[c];
        }
    }
    __syncthreads();

    if (tid < CC) {
        const int c = tid;
        float bv = -FLT_BIG;
        int   bi = 0x7fffffff;
        for (int ww = 0; ww < NW; ww++) {
            float v  = s_bval[ww * CC + c];
            int   ix = s_bidx[ww * CC + c];
            if (v > bv || (v == bv && ix < bi)) { bv = v; bi = ix; }
        }
        g_pval[(b * CC + c) * CH + chunk] = bv;
        g_pidx[(b * CC + c) * CH + chunk] = bi;
    }
}

// ---------------------------------------------------------------------------
// Kernel 2: merge chunk partials -> argmax (h,w); 3x3 clipped window mean;
// L2-normalize roi and cue; write output (B, 10, 768).
// Grid: (CC, BB). Block: 768 threads; thread t owns dim d = t.
// 9 predicated unrolled window loads -> full per-thread MLP (latency-bound kernel).
// ---------------------------------------------------------------------------
__global__ __launch_bounds__(768)
void pool_norm_kernel(const float* __restrict__ tokens, float* __restrict__ out)
{
    const int c   = blockIdx.x;
    const int b   = blockIdx.y;
    const int tid = threadIdx.x;

    __shared__ int   s_win[4];     // h0, h1, w0, w1
    __shared__ float s_red[50];

    if (tid == 0) {
        float bv = -FLT_BIG;
        int   bi = 0x7fffffff;
        for (int ch = 0; ch < CH; ch++) {
            float v  = g_pval[(b * CC + c) * CH + ch];
            int   ix = g_pidx[(b * CC + c) * CH + ch];
            if (v > bv || (v == bv && ix < bi)) { bv = v; bi = ix; }
        }
        const int h = bi / GG;
        const int w = bi % GG;
        s_win[0] = max(h - 1, 0);
        s_win[1] = min(h + 1, GG - 1);
        s_win[2] = max(w - 1, 0);
        s_win[3] = min(w + 1, GG - 1);
    }
    __syncthreads();

    const int h0 = s_win[0], h1 = s_win[1], w0 = s_win[2], w1 = s_win[3];
    const float inv_count = 1.0f / (float)((h1 - h0 + 1) * (w1 - w0 + 1));
    const float* tb = tokens + (size_t)b * SS * DD;
    const int d = tid;

    // 9 predicated loads, fully unrolled (window is 2x2..3x3 after clipping)
    float s = 0.0f;
#pragma unroll
    for (int hh = 0; hh < 3; hh++) {
#pragma unroll
        for (int ww = 0; ww < 3; ww++) {
            const int h = h0 + hh;
            const int w = w0 + ww;
            float val = 0.0f;
            if (h <= h1 && w <= w1)
                val = tb[(size_t)(5 + h * GG + w) * DD + d];
            s += val;
        }
    }
    const float roi = s * inv_count;
    const float q   = tb[(size_t)c * DD + d];

    float sr = roi * roi;
    float sq = q * q;
#pragma unroll
    for (int o = 16; o; o >>= 1) {
        sr += __shfl_xor_sync(0xffffffffu, sr, o);
        sq += __shfl_xor_sync(0xffffffffu, sq, o);
    }
    const int w = tid >> 5, lane = tid & 31;
    if (lane == 0) { s_red[w] = sr; s_red[24 + w] = sq; }
    __syncthreads();
    if (tid == 0) {
        float a = 0.0f, bs = 0.0f;
        for (int i = 0; i < 24; i++) { a += s_red[i]; bs += s_red[24 + i]; }
        s_red[48] = a;
        s_red[49] = bs;
    }
    __syncthreads();

    const float rinv = 1.0f / fmaxf(sqrtf(s_red[48]), 1e-12f);
    const float qinv = 1.0f / fmaxf(sqrtf(s_red[49]), 1e-12f);

    float* ob = out + (size_t)b * 10 * DD;
    ob[(size_t)c * DD + d]       = q * qinv;      // normalized cue
    ob[(size_t)(5 + c) * DD + d] = roi * rinv;    // normalized roi
}

extern "C" void kernel_launch(void* const* d_in, const int* in_sizes, int n_in,
                              void* d_out, int out_size)
{
    const float* tokens = (const float*)d_in[0];
    float* out = (float*)d_out;

    dim3 g1(BB, CH);     // 128 x 8 = 1024 blocks
    sim_argmax_kernel<<<g1, 256>>>(tokens);

    dim3 g2(CC, BB);     // 5 x 128 = 640 blocks
    pool_norm_kernel<<<g2, 768>>>(tokens, out);
}

// round 11
// speedup vs baseline: 1.8356x; 1.1362x over previous
#include <cuda_runtime.h>
#include <math.h>

#define BB   128
#define GG   37
#define NP   (GG*GG)          // 1369 patches
#define DD   768
#define CC   5                // cues: cls + 4 regs
#define SS   (1 + 4 + NP)     // 1374 tokens per batch
#define CH   9                // patch chunks per batch: 128*9 = 1152 blocks = 592+560 (balanced waves)
#define CPB  ((NP + CH - 1) / CH)   // 153 patches per chunk
#define NW   8                // warps per block
#define PP   4                // patches per warp per inner iteration
#define FLT_BIG 3.402823466e38f

// Cross-kernel scratch: per (batch, cue, chunk) partial argmax.
__device__ float g_pval[BB * CC * CH];
__device__ int   g_pidx[BB * CC * CH];

// ---------------------------------------------------------------------------
// Kernel 1: streaming dot-products cue[c] . patch[p], per-chunk argmax.
// Grid: (BB, CH). Block: 256 threads (8 warps).
// __launch_bounds__(256, 4): cap regs ~64 so 4 CTAs (32 warps) fit per SM.
// Patch rows are streamed with __ldcs (evict-first: zero reuse).
// ---------------------------------------------------------------------------
__global__ __launch_bounds__(256, 4)
void sim_argmax_kernel(const float* __restrict__ tokens)
{
    __shared__ float cue_s[CC * DD];     // 15360 B
    __shared__ float s_bval[NW * CC];
    __shared__ int   s_bidx[NW * CC];

    const int b     = blockIdx.x;
    const int chunk = blockIdx.y;
    const int tid   = threadIdx.x;
    const int w     = tid >> 5;
    const int lane  = tid & 31;

    const float* tb = tokens + (size_t)b * SS * DD;

    // stage the 5 cue rows (tokens s = 0..4) into shared memory
    for (int i = tid; i < CC * DD; i += 256) cue_s[i] = tb[i];
    __syncthreads();

    const int start = chunk * CPB;
    const int end   = min(start + CPB, NP);

    float bval[CC];
    int   bidx[CC];
#pragma unroll
    for (int c = 0; c < CC; c++) { bval[c] = -FLT_BIG; bidx[c] = 0x7fffffff; }

    const float4* cue4 = reinterpret_cast<const float4*>(cue_s);
    const float4* pb4  = reinterpret_cast<const float4*>(tb + 5 * DD);

    for (int base = start + w * PP; base < end; base += NW * PP) {

        float acc[CC][PP];
#pragma unroll
        for (int c = 0; c < CC; c++)
#pragma unroll
            for (int i = 0; i < PP; i++) acc[c][i] = 0.0f;

        // limited unroll keeps only one j-step of patch data (16 regs) live
#pragma unroll 2
        for (int j = 0; j < 6; j++) {              // 6 * 32 float4 = 768 floats
            const int off = j * 32 + lane;
            float4 v[PP];
#pragma unroll
            for (int i = 0; i < PP; i++) {
                // predicated streaming load: tail lanes contribute 0, no traffic
                if (base + i < end) {
                    v[i] = __ldcs(&pb4[(size_t)(base + i) * 192 + off]);
                } else {
                    v[i] = make_float4(0.f, 0.f, 0.f, 0.f);
                }
            }
#pragma unroll
            for (int c = 0; c < CC; c++) {
                const float4 q = cue4[c * 192 + off];
#pragma unroll
                for (int i = 0; i < PP; i++) {
                    acc[c][i] += v[i].x * q.x + v[i].y * q.y
                               + v[i].z * q.z + v[i].w * q.w;
                }
            }
        }

        // warp-butterfly reduce each of the 20 partial dots; result in all lanes
#pragma unroll
        for (int c = 0; c < CC; c++) {
#pragma unroll
            for (int i = 0; i < PP; i++) {
                float v = acc[c][i];
                v += __shfl_xor_sync(0xffffffffu, v, 16);
                v += __shfl_xor_sync(0xffffffffu, v, 8);
                v += __shfl_xor_sync(0xffffffffu, v, 4);
                v += __shfl_xor_sync(0xffffffffu, v, 2);
                v += __shfl_xor_sync(0xffffffffu, v, 1);
                const int p = base + i;
                if (p < end) {
                    if (v > bval[c] || (v == bval[c] && p < bidx[c])) {
                        bval[c] = v;
                        bidx[c] = p;
                    }
                }
            }
        }
    }

    if (lane == 0) {
#pragma unroll
        for (int c = 0; c < CC; c++) {
            s_bval[w * CC + c] = bval[c];
            s_bidx[w * CC + c] = bidx[c];
        }
    }
    __syncthreads();

    if (tid < CC) {
        const int c = tid;
        float bv = -FLT_BIG;
        int   bi = 0x7fffffff;
        for (int ww = 0; ww < NW; ww++) {
            float v  = s_bval[ww * CC + c];
            int   ix = s_bidx[ww * CC + c];
            if (v > bv || (v == bv && ix < bi)) { bv = v; bi = ix; }
        }
        g_pval[(b * CC + c) * CH + chunk] = bv;
        g_pidx[(b * CC + c) * CH + chunk] = bi;
    }
}

// ---------------------------------------------------------------------------
// Kernel 2: merge chunk partials (parallel, warp 0) -> argmax (h,w);
// 3x3 clipped window mean; L2-normalize roi and cue; write (B, 10, 768).
// Grid: (CC, BB). Block: 768 threads; thread t owns dim d = t.
// ---------------------------------------------------------------------------
__global__ __launch_bounds__(768)
void pool_norm_kernel(const float* __restrict__ tokens, float* __restrict__ out)
{
    const int c   = blockIdx.x;
    const int b   = blockIdx.y;
    const int tid = threadIdx.x;
    const int d   = tid;

    __shared__ int   s_win[4];     // h0, h1, w0, w1
    __shared__ float s_red[50];

    const float* tb = tokens + (size_t)b * SS * DD;

    // issue the cue load before the merge/sync so it overlaps the chain
    const float q = tb[(size_t)c * DD + d];

    // parallel merge of CH chunk partials across warp-0 lanes
    if (tid < 32) {
        float bv = -FLT_BIG;
        int   bi = 0x7fffffff;
        if (tid < CH) {
            bv = g_pval[(b * CC + c) * CH + tid];
            bi = g_pidx[(b * CC + c) * CH + tid];
        }
#pragma unroll
        for (int o = 16; o; o >>= 1) {
            float ov = __shfl_xor_sync(0xffffffffu, bv, o);
            int   oi = __shfl_xor_sync(0xffffffffu, bi, o);
            if (ov > bv || (ov == bv && oi < bi)) { bv = ov; bi = oi; }
        }
        if (tid == 0) {
            const int h = bi / GG;
            const int w = bi % GG;
            s_win[0] = max(h - 1, 0);
            s_win[1] = min(h + 1, GG - 1);
            s_win[2] = max(w - 1, 0);
            s_win[3] = min(w + 1, GG - 1);
        }
    }
    __syncthreads();

    const int h0 = s_win[0], h1 = s_win[1], w0 = s_win[2], w1 = s_win[3];
    const float inv_count = 1.0f / (float)((h1 - h0 + 1) * (w1 - w0 + 1));

    // 9 predicated loads, fully unrolled (window is 2x2..3x3 after clipping)
    float s = 0.0f;
#pragma unroll
    for (int hh = 0; hh < 3; hh++) {
#pragma unroll
        for (int ww = 0; ww < 3; ww++) {
            const int h = h0 + hh;
            const int w = w0 + ww;
            float val = 0.0f;
            if (h <= h1 && w <= w1)
                val = tb[(size_t)(5 + h * GG + w) * DD + d];
            s += val;
        }
    }
    const float roi = s * inv_count;

    float sr = roi * roi;
    float sq = q * q;
#pragma unroll
    for (int o = 16; o; o >>= 1) {
        sr += __shfl_xor_sync(0xffffffffu, sr, o);
        sq += __shfl_xor_sync(0xffffffffu, sq, o);
    }
    const int w = tid >> 5, lane = tid & 31;
    if (lane == 0) { s_red[w] = sr; s_red[24 + w] = sq; }
    __syncthreads();
    if (tid == 0) {
        float a = 0.0f, bs = 0.0f;
        for (int i = 0; i < 24; i++) { a += s_red[i]; bs += s_red[24 + i]; }
        s_red[48] = a;
        s_red[49] = bs;
    }
    __syncthreads();

    const float rinv = 1.0f / fmaxf(sqrtf(s_red[48]), 1e-12f);
    const float qinv = 1.0f / fmaxf(sqrtf(s_red[49]), 1e-12f);

    float* ob = out + (size_t)b * 10 * DD;
    ob[(size_t)c * DD + d]       = q * qinv;      // normalized cue
    ob[(size_t)(5 + c) * DD + d] = roi * rinv;    // normalized roi
}

extern "C" void kernel_launch(void* const* d_in, const int* in_sizes, int n_in,
                              void* d_out, int out_size)
{
    const float* tokens = (const float*)d_in[0];
    float* out = (float*)d_out;

    dim3 g1(BB, CH);     // 128 x 9 = 1152 blocks (2 balanced waves at 4 CTA/SM)
    sim_argmax_kernel<<<g1, 256>>>(tokens);

    dim3 g2(CC, BB);     // 5 x 128 = 640 blocks
    pool_norm_kernel<<<g2, 768>>>(tokens, out);
}